// round 11
// baseline (speedup 1.0000x reference)
#include <cuda_runtime.h>
#include <cuda_bf16.h>
#include <math.h>

// Problem constants (fixed by setup_inputs)
#define BATCH   16
#define LEN     262144
#define NFFT    1024
#define HOP     256
#define NT      1025          // frames
#define NF      513           // rfft bins (valid)
#define NTP     65            // time patches
#define NFP     33            // freq patches
#define NP      2145          // patches per batch (33*65)
#define KSEL    643           // int(2145*0.3)
#define REFL2   (2*LEN - 2)   // 524286

// Scratch (static device memory; no allocation allowed)
__device__ float g_part[(size_t)BATCH * NFP * NTP * 4 * 3];  // per-quarter partial sums
__device__ float g_bsel[BATCH];
__device__ float g_bkgs[BATCH];
__device__ int   g_bpos[BATCH];
__device__ float2 g_twa[64];     // W64^{n1*c}
__device__ float2 g_twb[512];    // [c*64+t] = W512^{n0*(k0+8c)}
__device__ float2 g_twu[512];    // e^{-i pi j/512}

// ---- complex helpers (float2) ----
__device__ __forceinline__ float2 cadd(float2 a, float2 b) { return make_float2(a.x + b.x, a.y + b.y); }
__device__ __forceinline__ float2 csub(float2 a, float2 b) { return make_float2(a.x - b.x, a.y - b.y); }
__device__ __forceinline__ float2 cmul(float2 a, float2 b) {
    return make_float2(a.x * b.x - a.y * b.y, a.x * b.y + a.y * b.x);
}
__device__ __forceinline__ float2 cmni(float2 a) { return make_float2(a.y, -a.x); }  // * (-i)

// FFT-8, natural-order in/out, straight-line on named registers.
__device__ __forceinline__ void fft8(float2& a0, float2& a1, float2& a2, float2& a3,
                                     float2& a4, float2& a5, float2& a6, float2& a7) {
    float2 ee0 = cadd(a0, a4), ee1 = csub(a0, a4);
    float2 oo0 = cadd(a2, a6), oo1 = csub(a2, a6);
    float2 E0 = cadd(ee0, oo0), E2 = csub(ee0, oo0);
    float2 tm = cmni(oo1);
    float2 E1 = cadd(ee1, tm), E3 = csub(ee1, tm);
    float2 fe0 = cadd(a1, a5), fe1 = csub(a1, a5);
    float2 fo0 = cadd(a3, a7), fo1 = csub(a3, a7);
    float2 O0 = cadd(fe0, fo0), O2 = csub(fe0, fo0);
    float2 um = cmni(fo1);
    float2 O1 = cadd(fe1, um), O3 = csub(fe1, um);
    const float s = 0.70710678118654752f;
    float2 w1o = make_float2(s * (O1.x + O1.y), s * (O1.y - O1.x));   // w8 * O1
    float2 w3o = make_float2(s * (O3.y - O3.x), -s * (O3.x + O3.y));  // w8^3 * O3
    float2 m2  = cmni(O2);
    a0 = cadd(E0, O0);  a4 = csub(E0, O0);
    a1 = cadd(E1, w1o); a5 = csub(E1, w1o);
    a2 = cadd(E2, m2);  a6 = csub(E2, m2);
    a3 = cadd(E3, w3o); a7 = csub(E3, w3o);
}

// group barrier: 64 threads (2 warps) of signal-group grp, named barrier 1..3
#define GBAR(grp) asm volatile("bar.sync %0, 64;" :: "r"((grp) + 1) : "memory")

// ---------------------------------------------------------------------------
// Init: build twiddle tables ONCE per launch (idempotent, deterministic).
// ---------------------------------------------------------------------------
__global__ void init_tw() {
    int idx = blockIdx.x * 128 + threadIdx.x;
    float sn, cs;
    if (idx < 64) {
        int n1 = idx >> 3, c = idx & 7;
        sincospif(-(float)(n1 * c) * (1.0f / 32.0f), &sn, &cs);
        g_twa[idx] = make_float2(cs, sn);
    } else if (idx < 576) {
        int e = idx - 64; int c = e >> 6; int t_ = e & 63;
        int n0b = t_ & 7, k0 = t_ >> 3;
        sincospif(-(float)(n0b * (k0 + 8 * c)) * (1.0f / 256.0f), &sn, &cs);
        g_twb[e] = make_float2(cs, sn);
    } else if (idx < 1088) {
        int j = idx - 576;
        sincospif(-(float)j * (1.0f / 512.0f), &sn, &cs);
        g_twu[j] = make_float2(cs, sn);
    }
}

// ---------------------------------------------------------------------------
// Fused STFT + patch kernel. Block = (batch b, time-patch tp, quarter q);
// 192 threads = 3 signal-groups x 64. Each of (up to) 4 frames: rfft-1024 via
// complex FFT-512 (radix 8x8x8) per signal, untangle magnitudes to shared,
// accumulate per-f-patch |s-g|, |t-g|, (s-t)^2. Quarters write disjoint
// partials to g_part. Twiddles copied global->shared (cheap, L2-broadcast).
// ---------------------------------------------------------------------------
__global__ __launch_bounds__(192, 5) void fused_kernel(
    const float* __restrict__ xs, const float* __restrict__ xt,
    const float* __restrict__ xg)
{
    const int tid = threadIdx.x;
    const int grp = tid / 64;          // which signal
    const int t64 = tid & 63;
    const int q   = blockIdx.x & 3;
    const int bt  = blockIdx.x >> 2;
    const int b   = bt / NTP;
    const int tp  = bt - b * NTP;

    __shared__ float2 SH[3][2][576];   // per-signal ping-pong FFT slabs
    __shared__ float2 tw_a[64];        // W64^{n1*c}
    __shared__ float2 tw_b[512];       // [c*64+t64] = W512^{n0*(k0+8c)}
    __shared__ float2 tw_u[512];       // e^{-i pi j/512}
    __shared__ float  pacc[NFP][4];    // per-f-patch sums: S, T, P

    // ---- copy twiddle tables from global (built by init_tw) ----
    for (int idx = tid; idx < 1088; idx += 192) {
        if (idx < 64)       tw_a[idx]       = g_twa[idx];
        else if (idx < 576) tw_b[idx - 64]  = g_twb[idx - 64];
        else                tw_u[idx - 576] = g_twu[idx - 576];
    }
    if (tid < NFP) { pacc[tid][0] = 0.f; pacc[tid][1] = 0.f; pacc[tid][2] = 0.f; }
    __syncthreads();

    const float* x = (grp == 0 ? xs : (grp == 1 ? xt : xg)) + (size_t)b * LEN;
    float2* buf0 = SH[grp][0];
    float2* buf1 = SH[grp][1];

    const int n1A = t64 >> 3;          // step-A row
    const int n0A = t64 & 7;

    // per-thread patch accumulators (f = tid, tid+192, tid+384)
    float aS0 = 0.f, aT0 = 0.f, aP0 = 0.f;
    float aS1 = 0.f, aT1 = 0.f, aP1 = 0.f;
    float aS2 = 0.f, aT2 = 0.f, aP2 = 0.f;

    const int t0 = tp * 16 + q * 4;
    for (int it = 0; it < 4; it++) {
        const int t = t0 + it;
        if (t >= NT) break;                          // uniform across block
        const int F = t * HOP - 512;

        // ---- load z[n] = x[2n] + i x[2n+1], n = t64 + 64*k ----
        float2 a0, a1, a2, a3, a4, a5, a6, a7;
        if (F >= 0 && F + NFFT <= LEN) {
            const float2* x2 = (const float2*)(x + F);
            a0 = x2[t64];       a1 = x2[t64 + 64];  a2 = x2[t64 + 128]; a3 = x2[t64 + 192];
            a4 = x2[t64 + 256]; a5 = x2[t64 + 320]; a6 = x2[t64 + 384]; a7 = x2[t64 + 448];
        } else {
#define LOADR(dst, K) { int g = F + 2 * (t64 + 64 * (K));                          \
            int i0 = min(abs(g), REFL2 - g); int i1 = min(abs(g + 1), REFL2 - g - 1); \
            dst = make_float2(x[i0], x[i1]); }
            LOADR(a0, 0) LOADR(a1, 1) LOADR(a2, 2) LOADR(a3, 3)
            LOADR(a4, 4) LOADR(a5, 5) LOADR(a6, 6) LOADR(a7, 7)
#undef LOADR
        }

        // ---- step A: FFT8 over n2; twiddle from table ----
        fft8(a0, a1, a2, a3, a4, a5, a6, a7);
        a1 = cmul(a1, tw_a[n1A * 8 + 1]);
        a2 = cmul(a2, tw_a[n1A * 8 + 2]);
        a3 = cmul(a3, tw_a[n1A * 8 + 3]);
        a4 = cmul(a4, tw_a[n1A * 8 + 4]);
        a5 = cmul(a5, tw_a[n1A * 8 + 5]);
        a6 = cmul(a6, tw_a[n1A * 8 + 6]);
        a7 = cmul(a7, tw_a[n1A * 8 + 7]);
        {
            const int wi = n1A * 9 + n0A;
            buf0[wi]       = a0; buf0[wi + 72]  = a1; buf0[wi + 144] = a2; buf0[wi + 216] = a3;
            buf0[wi + 288] = a4; buf0[wi + 360] = a5; buf0[wi + 432] = a6; buf0[wi + 504] = a7;
        }
        GBAR(grp);

        // ---- step B: gather over n1; FFT8; twiddle from table ----
        {
            const int n0b = t64 & 7;
            const int k0  = t64 >> 3;
            const int rb  = k0 * 72 + n0b;
            float2 b0 = buf0[rb];      float2 b1 = buf0[rb + 9];  float2 b2 = buf0[rb + 18];
            float2 b3 = buf0[rb + 27]; float2 b4 = buf0[rb + 36]; float2 b5 = buf0[rb + 45];
            float2 b6 = buf0[rb + 54]; float2 b7 = buf0[rb + 63];
            fft8(b0, b1, b2, b3, b4, b5, b6, b7);
            b0 = cmul(b0, tw_b[t64]);
            b1 = cmul(b1, tw_b[64  + t64]);
            b2 = cmul(b2, tw_b[128 + t64]);
            b3 = cmul(b3, tw_b[192 + t64]);
            b4 = cmul(b4, tw_b[256 + t64]);
            b5 = cmul(b5, tw_b[320 + t64]);
            b6 = cmul(b6, tw_b[384 + t64]);
            b7 = cmul(b7, tw_b[448 + t64]);
            const int wb = k0 * 9 + n0b;
            buf1[wb]       = b0; buf1[wb + 72]  = b1; buf1[wb + 144] = b2; buf1[wb + 216] = b3;
            buf1[wb + 288] = b4; buf1[wb + 360] = b5; buf1[wb + 432] = b6; buf1[wb + 504] = b7;
        }
        GBAR(grp);

        // ---- step C: gather over n0; FFT8 -> Z; publish to buf0 ----
        {
            const int k0c = t64 & 7;
            const int k1  = t64 >> 3;
            const int rc  = k1 * 72 + k0c * 9;
            float2 c0 = buf1[rc];     float2 c1 = buf1[rc + 1]; float2 c2 = buf1[rc + 2];
            float2 c3 = buf1[rc + 3]; float2 c4 = buf1[rc + 4]; float2 c5 = buf1[rc + 5];
            float2 c6 = buf1[rc + 6]; float2 c7 = buf1[rc + 7];
            fft8(c0, c1, c2, c3, c4, c5, c6, c7);
            buf0[t64]       = c0; buf0[t64 + 64]  = c1; buf0[t64 + 128] = c2; buf0[t64 + 192] = c3;
            buf0[t64 + 256] = c4; buf0[t64 + 320] = c5; buf0[t64 + 384] = c6; buf0[t64 + 448] = c7;
        }
        GBAR(grp);

        // ---- untangle rfft + magnitude into shared (reuse buf1 as float*) ----
        {
            float* mg = (float*)buf1;
#pragma unroll
            for (int c = 0; c < 8; c++) {
                int j = t64 + 64 * c;
                float2 Zj = buf0[j];
                float2 Zm = buf0[(512 - j) & 511];
                float2 w  = tw_u[j];
                float ex = 0.5f * (Zj.x + Zm.x), ey = 0.5f * (Zj.y - Zm.y);
                float dx = 0.5f * (Zj.x - Zm.x), dy = 0.5f * (Zj.y + Zm.y);
                float ox = dy, oy = -dx;
                float xr_ = ex + (w.x * ox - w.y * oy);
                float xi_ = ey + (w.x * oy + w.y * ox);
                mg[j] = fmaxf(sqrtf(xr_ * xr_ + xi_ * xi_), 1e-8f);
            }
            if (t64 == 0) {
                float2 Z0 = buf0[0];
                mg[512] = fmaxf(fabsf(Z0.x - Z0.y), 1e-8f);
            }
        }
        __syncthreads();    // all three signals' magnitudes ready

        // ---- accumulate patch partial sums (all 192 threads) ----
        {
            const float* ms = (const float*)SH[0][1];
            const float* mt = (const float*)SH[1][1];
            const float* mgd = (const float*)SH[2][1];
            {
                int f = tid;                       // 0..191
                float s = ms[f], tt = mt[f], g = mgd[f];
                aS0 += fabsf(s - g); aT0 += fabsf(tt - g);
                float d = s - tt; aP0 += d * d;
            }
            {
                int f = tid + 192;                 // 192..383
                float s = ms[f], tt = mt[f], g = mgd[f];
                aS1 += fabsf(s - g); aT1 += fabsf(tt - g);
                float d = s - tt; aP1 += d * d;
            }
            if (tid + 384 < NF) {                  // 384..512
                int f = tid + 384;
                float s = ms[f], tt = mt[f], g = mgd[f];
                aS2 += fabsf(s - g); aT2 += fabsf(tt - g);
                float d = s - tt; aP2 += d * d;
            }
        }
        __syncthreads();   // protect bufs before next iteration
    }

    // ---- fold per-thread accumulators into per-f-patch sums ----
    {
        int f0 = tid;
        atomicAdd(&pacc[f0 >> 4][0], aS0);
        atomicAdd(&pacc[f0 >> 4][1], aT0);
        atomicAdd(&pacc[f0 >> 4][2], aP0);
        int f1 = tid + 192;
        atomicAdd(&pacc[f1 >> 4][0], aS1);
        atomicAdd(&pacc[f1 >> 4][1], aT1);
        atomicAdd(&pacc[f1 >> 4][2], aP1);
        if (tid + 384 < NF) {
            int f2 = tid + 384;
            atomicAdd(&pacc[f2 >> 4][0], aS2);
            atomicAdd(&pacc[f2 >> 4][1], aT2);
            atomicAdd(&pacc[f2 >> 4][2], aP2);
        }
    }
    __syncthreads();

    if (tid < NFP) {
        // g_part layout: [b][fp][tp][q][3]
        size_t o = (((size_t)(b * NFP + tid) * NTP + tp) * 4 + q) * 3;
        g_part[o + 0] = pacc[tid][0];
        g_part[o + 1] = pacc[tid][1];
        g_part[o + 2] = pacc[tid][2];
    }
}

// ---------------------------------------------------------------------------
// Kernel 3: per-batch top-k selection (exact, index-order tie-break) + stats
// ---------------------------------------------------------------------------
__device__ __forceinline__ int bredI(int v, int* scr) {
    const int tid = threadIdx.x;
#pragma unroll
    for (int o = 16; o; o >>= 1) v += __shfl_down_sync(0xffffffffu, v, o);
    __syncthreads();
    if ((tid & 31) == 0) scr[tid >> 5] = v;
    __syncthreads();
    int r = 0;
#pragma unroll
    for (int j = 0; j < 8; j++) r += scr[j];
    return r;
}
__device__ __forceinline__ float bredF(float v, float* scr) {
    const int tid = threadIdx.x;
#pragma unroll
    for (int o = 16; o; o >>= 1) v += __shfl_down_sync(0xffffffffu, v, o);
    __syncthreads();
    if ((tid & 31) == 0) scr[tid >> 5] = v;
    __syncthreads();
    float r = 0.f;
#pragma unroll
    for (int j = 0; j < 8; j++) r += scr[j];
    return r;
}

__global__ __launch_bounds__(256) void select_kernel() {
    const int b = blockIdx.x, tid = threadIdx.x;
    __shared__ unsigned su[NP];
    __shared__ float    spl[NP];
    __shared__ int      eqidx[NP];
    __shared__ int      iscr[8];
    __shared__ float    fscr[8];
    __shared__ int      eqc;

    float ksum = 0.f; int pcnt = 0;
    for (int i = tid; i < NP; i += 256) {
        const float* pp = g_part + ((size_t)b * NP + i) * 12;
        float S = (pp[0] + pp[3]) + (pp[6] + pp[9]);
        float T = (pp[1] + pp[4]) + (pp[7] + pp[10]);
        float P = (pp[2] + pp[5]) + (pp[8] + pp[11]);
        float kv = (S - T) * (1.0f / 256.0f);
        spl[i] = P * (1.0f / 256.0f);
        unsigned bits = __float_as_uint(kv);
        su[i] = (bits & 0x80000000u) ? ~bits : (bits | 0x80000000u); // order-preserving
        ksum += kv;
        pcnt += (kv > 0.f) ? 1 : 0;
    }
    if (tid == 0) eqc = 0;
    __syncthreads();

    ksum = bredF(ksum, fscr);
    pcnt = bredI(pcnt, iscr);

    // binary search for k-th largest key: max v with count(u >= v) >= KSEL
    unsigned long long lo = 0ull, hi = 0xFFFFFFFFull;
    while (lo < hi) {
        unsigned long long mid = lo + ((hi - lo + 1ull) >> 1);
        int c = 0;
        for (int i = tid; i < NP; i += 256)
            c += ((unsigned long long)su[i] >= mid) ? 1 : 0;
        c = bredI(c, iscr);
        if (c >= KSEL) lo = mid; else hi = mid - 1ull;
    }
    const unsigned v = (unsigned)lo;

    int cgt = 0; float ssel = 0.f;
    for (int i = tid; i < NP; i += 256) {
        unsigned u = su[i];
        if (u > v) { cgt++; ssel += spl[i]; }
        else if (u == v) { int pos = atomicAdd(&eqc, 1); eqidx[pos] = i; }
    }
    cgt  = bredI(cgt, iscr);
    ssel = bredF(ssel, fscr);
    __syncthreads();

    if (tid == 0) {
        int need = KSEL - cgt;         // >= 1 by construction
        int ce   = eqc;
        float extra = 0.f;
        if (need >= ce) {
            for (int j = 0; j < ce; j++) extra += spl[eqidx[j]];
        } else {
            int last = -1;
            for (int t2 = 0; t2 < need; t2++) {
                int mn = 0x7fffffff;
                for (int j = 0; j < ce; j++) {
                    int ix = eqidx[j];
                    if (ix > last && ix < mn) mn = ix;
                }
                extra += spl[mn];
                last = mn;
            }
        }
        g_bsel[b] = (ssel + extra) * (1.0f / (float)KSEL);
        g_bkgs[b] = ksum;
        g_bpos[b] = pcnt;
    }
}

// ---------------------------------------------------------------------------
// Kernel 4: finalize the 4 scalars
// ---------------------------------------------------------------------------
__global__ void final_kernel(float* __restrict__ out) {
    const int t = threadIdx.x;
    float s  = (t < BATCH) ? g_bsel[t] : 0.f;
    float kg = (t < BATCH) ? g_bkgs[t] : 0.f;
    float pc = (t < BATCH) ? (float)g_bpos[t] : 0.f;
#pragma unroll
    for (int o = 16; o; o >>= 1) {
        s  += __shfl_down_sync(0xffffffffu, s,  o);
        kg += __shfl_down_sync(0xffffffffu, kg, o);
        pc += __shfl_down_sync(0xffffffffu, pc, o);
    }
    if (t == 0) {
        out[0] = s * (1.0f / (float)BATCH);                      // loss
        out[1] = (float)KSEL / (float)NP;                        // sel_ratio
        out[2] = kg / (float)(BATCH * NP);                       // kgs_mean
        out[3] = pc / (float)(BATCH * NP);                       // kgs_pos_ratio
    }
}

extern "C" void kernel_launch(void* const* d_in, const int* in_sizes, int n_in,
                              void* d_out, int out_size) {
    const float* xs = (const float*)d_in[0];
    const float* xt = (const float*)d_in[1];
    const float* xg = (const float*)d_in[2];
    float* out = (float*)d_out;

    init_tw<<<9, 128>>>();                                 // ~2us, once per call
    fused_kernel<<<BATCH * NTP * 4, 192>>>(xs, xt, xg);    // 4160 blocks
    select_kernel<<<BATCH, 256>>>();
    final_kernel<<<1, 32>>>(out);
}

// round 12
// speedup vs baseline: 1.1937x; 1.1937x over previous
#include <cuda_runtime.h>
#include <cuda_bf16.h>
#include <math.h>

// Problem constants (fixed by setup_inputs)
#define BATCH   16
#define LEN     262144
#define NFFT    1024
#define HOP     256
#define NT      1025          // frames
#define NF      513           // rfft bins (valid)
#define NTP     65            // time patches
#define NFP     33            // freq patches
#define NP      2145          // patches per batch (33*65)
#define KSEL    643           // int(2145*0.3)
#define REFL2   (2*LEN - 2)   // 524286

// Scratch (static device memory; no allocation allowed)
__device__ float g_part[(size_t)BATCH * NTP * NFP * 3];  // [pt=b*NTP+tp][fp][3]
__device__ float g_bsel[BATCH];
__device__ float g_bkgs[BATCH];
__device__ int   g_bpos[BATCH];
__device__ float2 g_twa[64];     // W64^{n1*c}
__device__ float2 g_twb[512];    // [c*64+t] = W512^{n0*(k0+8c)}
__device__ float2 g_twu[512];    // e^{-i pi j/512}

// ---- complex helpers (float2) ----
__device__ __forceinline__ float2 cadd(float2 a, float2 b) { return make_float2(a.x + b.x, a.y + b.y); }
__device__ __forceinline__ float2 csub(float2 a, float2 b) { return make_float2(a.x - b.x, a.y - b.y); }
__device__ __forceinline__ float2 cmul(float2 a, float2 b) {
    return make_float2(a.x * b.x - a.y * b.y, a.x * b.y + a.y * b.x);
}
__device__ __forceinline__ float2 cmni(float2 a) { return make_float2(a.y, -a.x); }  // * (-i)

// FFT-8, natural-order in/out, straight-line on named registers.
__device__ __forceinline__ void fft8(float2& a0, float2& a1, float2& a2, float2& a3,
                                     float2& a4, float2& a5, float2& a6, float2& a7) {
    float2 ee0 = cadd(a0, a4), ee1 = csub(a0, a4);
    float2 oo0 = cadd(a2, a6), oo1 = csub(a2, a6);
    float2 E0 = cadd(ee0, oo0), E2 = csub(ee0, oo0);
    float2 tm = cmni(oo1);
    float2 E1 = cadd(ee1, tm), E3 = csub(ee1, tm);
    float2 fe0 = cadd(a1, a5), fe1 = csub(a1, a5);
    float2 fo0 = cadd(a3, a7), fo1 = csub(a3, a7);
    float2 O0 = cadd(fe0, fo0), O2 = csub(fe0, fo0);
    float2 um = cmni(fo1);
    float2 O1 = cadd(fe1, um), O3 = csub(fe1, um);
    const float s = 0.70710678118654752f;
    float2 w1o = make_float2(s * (O1.x + O1.y), s * (O1.y - O1.x));   // w8 * O1
    float2 w3o = make_float2(s * (O3.y - O3.x), -s * (O3.x + O3.y));  // w8^3 * O3
    float2 m2  = cmni(O2);
    a0 = cadd(E0, O0);  a4 = csub(E0, O0);
    a1 = cadd(E1, w1o); a5 = csub(E1, w1o);
    a2 = cadd(E2, m2);  a6 = csub(E2, m2);
    a3 = cadd(E3, w3o); a7 = csub(E3, w3o);
}

// group barrier: 64 threads (2 warps) of signal-group grp, named barrier 1..3
#define GBAR(grp) asm volatile("bar.sync %0, 64;" :: "r"((grp) + 1) : "memory")

// ---------------------------------------------------------------------------
// Init: build twiddle tables ONCE per launch (idempotent, deterministic).
// ---------------------------------------------------------------------------
__global__ void init_tw() {
    int idx = blockIdx.x * 128 + threadIdx.x;
    float sn, cs;
    if (idx < 64) {
        int n1 = idx >> 3, c = idx & 7;
        sincospif(-(float)(n1 * c) * (1.0f / 32.0f), &sn, &cs);
        g_twa[idx] = make_float2(cs, sn);
    } else if (idx < 576) {
        int e = idx - 64; int c = e >> 6; int t_ = e & 63;
        int n0b = t_ & 7, k0 = t_ >> 3;
        sincospif(-(float)(n0b * (k0 + 8 * c)) * (1.0f / 256.0f), &sn, &cs);
        g_twb[e] = make_float2(cs, sn);
    } else if (idx < 1088) {
        int j = idx - 576;
        sincospif(-(float)j * (1.0f / 512.0f), &sn, &cs);
        g_twu[j] = make_float2(cs, sn);
    }
}

// ---------------------------------------------------------------------------
// Fused STFT + patch kernel, SINGLE-WAVE schedule. Block = 2 consecutive
// (b,tp) units (32 frames); grid = 520 blocks -> all co-resident on 148 SMs,
// no wave quantization, perfectly uniform work. 192 threads = 3 signal
// groups x 64. Per frame: rfft-1024 via complex FFT-512 (radix 8x8x8),
// untangle magnitudes to shared, accumulate per-f-patch sums in registers.
// ---------------------------------------------------------------------------
__global__ __launch_bounds__(192, 5) void fused_kernel(
    const float* __restrict__ xs, const float* __restrict__ xt,
    const float* __restrict__ xg)
{
    const int tid = threadIdx.x;
    const int grp = tid / 64;          // which signal
    const int t64 = tid & 63;

    __shared__ float2 SH[3][2][576];   // per-signal ping-pong FFT slabs
    __shared__ float2 tw_a[64];
    __shared__ float2 tw_b[512];
    __shared__ float2 tw_u[512];
    __shared__ float  pacc[NFP][4];    // per-f-patch sums: S, T, P

    // ---- copy twiddle tables from global (built by init_tw) ----
    for (int idx = tid; idx < 1088; idx += 192) {
        if (idx < 64)       tw_a[idx]       = g_twa[idx];
        else if (idx < 576) tw_b[idx - 64]  = g_twb[idx - 64];
        else                tw_u[idx - 576] = g_twu[idx - 576];
    }

    float2* buf0 = SH[grp][0];
    float2* buf1 = SH[grp][1];
    const int n1A = t64 >> 3;          // step-A row
    const int n0A = t64 & 7;

    for (int h = 0; h < 2; h++) {
        const int pt = blockIdx.x * 2 + h;       // (b,tp) unit, 1040 total
        const int b  = pt / NTP;
        const int tp = pt - b * NTP;
        const float* x = (grp == 0 ? xs : (grp == 1 ? xt : xg)) + (size_t)b * LEN;

        if (tid < NFP) { pacc[tid][0] = 0.f; pacc[tid][1] = 0.f; pacc[tid][2] = 0.f; }

        // per-thread patch accumulators (f = tid, tid+192, tid+384)
        float aS0 = 0.f, aT0 = 0.f, aP0 = 0.f;
        float aS1 = 0.f, aT1 = 0.f, aP1 = 0.f;
        float aS2 = 0.f, aT2 = 0.f, aP2 = 0.f;

        __syncthreads();   // tables (h=0) / pacc zero visible; prev half done

        for (int it = 0; it < 16; it++) {
            const int t = tp * 16 + it;
            if (t >= NT) break;                      // uniform across block
            const int F = t * HOP - 512;

            // ---- load z[n] = x[2n] + i x[2n+1], n = t64 + 64*k ----
            float2 a0, a1, a2, a3, a4, a5, a6, a7;
            if (F >= 0 && F + NFFT <= LEN) {
                const float2* x2 = (const float2*)(x + F);
                a0 = x2[t64];       a1 = x2[t64 + 64];  a2 = x2[t64 + 128]; a3 = x2[t64 + 192];
                a4 = x2[t64 + 256]; a5 = x2[t64 + 320]; a6 = x2[t64 + 384]; a7 = x2[t64 + 448];
            } else {
#define LOADR(dst, K) { int g = F + 2 * (t64 + 64 * (K));                          \
                int i0 = min(abs(g), REFL2 - g); int i1 = min(abs(g + 1), REFL2 - g - 1); \
                dst = make_float2(x[i0], x[i1]); }
                LOADR(a0, 0) LOADR(a1, 1) LOADR(a2, 2) LOADR(a3, 3)
                LOADR(a4, 4) LOADR(a5, 5) LOADR(a6, 6) LOADR(a7, 7)
#undef LOADR
            }

            // ---- step A: FFT8 over n2; twiddle from table ----
            fft8(a0, a1, a2, a3, a4, a5, a6, a7);
            a1 = cmul(a1, tw_a[n1A * 8 + 1]);
            a2 = cmul(a2, tw_a[n1A * 8 + 2]);
            a3 = cmul(a3, tw_a[n1A * 8 + 3]);
            a4 = cmul(a4, tw_a[n1A * 8 + 4]);
            a5 = cmul(a5, tw_a[n1A * 8 + 5]);
            a6 = cmul(a6, tw_a[n1A * 8 + 6]);
            a7 = cmul(a7, tw_a[n1A * 8 + 7]);
            {
                const int wi = n1A * 9 + n0A;
                buf0[wi]       = a0; buf0[wi + 72]  = a1; buf0[wi + 144] = a2; buf0[wi + 216] = a3;
                buf0[wi + 288] = a4; buf0[wi + 360] = a5; buf0[wi + 432] = a6; buf0[wi + 504] = a7;
            }
            GBAR(grp);

            // ---- step B: gather over n1; FFT8; twiddle from table ----
            {
                const int n0b = t64 & 7;
                const int k0  = t64 >> 3;
                const int rb  = k0 * 72 + n0b;
                float2 b0 = buf0[rb];      float2 b1 = buf0[rb + 9];  float2 b2 = buf0[rb + 18];
                float2 b3 = buf0[rb + 27]; float2 b4 = buf0[rb + 36]; float2 b5 = buf0[rb + 45];
                float2 b6 = buf0[rb + 54]; float2 b7 = buf0[rb + 63];
                fft8(b0, b1, b2, b3, b4, b5, b6, b7);
                b0 = cmul(b0, tw_b[t64]);
                b1 = cmul(b1, tw_b[64  + t64]);
                b2 = cmul(b2, tw_b[128 + t64]);
                b3 = cmul(b3, tw_b[192 + t64]);
                b4 = cmul(b4, tw_b[256 + t64]);
                b5 = cmul(b5, tw_b[320 + t64]);
                b6 = cmul(b6, tw_b[384 + t64]);
                b7 = cmul(b7, tw_b[448 + t64]);
                const int wb = k0 * 9 + n0b;
                buf1[wb]       = b0; buf1[wb + 72]  = b1; buf1[wb + 144] = b2; buf1[wb + 216] = b3;
                buf1[wb + 288] = b4; buf1[wb + 360] = b5; buf1[wb + 432] = b6; buf1[wb + 504] = b7;
            }
            GBAR(grp);

            // ---- step C: gather over n0; FFT8 -> Z; publish to buf0 ----
            {
                const int k0c = t64 & 7;
                const int k1  = t64 >> 3;
                const int rc  = k1 * 72 + k0c * 9;
                float2 c0 = buf1[rc];     float2 c1 = buf1[rc + 1]; float2 c2 = buf1[rc + 2];
                float2 c3 = buf1[rc + 3]; float2 c4 = buf1[rc + 4]; float2 c5 = buf1[rc + 5];
                float2 c6 = buf1[rc + 6]; float2 c7 = buf1[rc + 7];
                fft8(c0, c1, c2, c3, c4, c5, c6, c7);
                buf0[t64]       = c0; buf0[t64 + 64]  = c1; buf0[t64 + 128] = c2; buf0[t64 + 192] = c3;
                buf0[t64 + 256] = c4; buf0[t64 + 320] = c5; buf0[t64 + 384] = c6; buf0[t64 + 448] = c7;
            }
            GBAR(grp);

            // ---- untangle rfft + magnitude into shared (buf1 as float*) ----
            {
                float* mg = (float*)buf1;
#pragma unroll
                for (int c = 0; c < 8; c++) {
                    int j = t64 + 64 * c;
                    float2 Zj = buf0[j];
                    float2 Zm = buf0[(512 - j) & 511];
                    float2 w  = tw_u[j];
                    float ex = 0.5f * (Zj.x + Zm.x), ey = 0.5f * (Zj.y - Zm.y);
                    float dx = 0.5f * (Zj.x - Zm.x), dy = 0.5f * (Zj.y + Zm.y);
                    float ox = dy, oy = -dx;
                    float xr_ = ex + (w.x * ox - w.y * oy);
                    float xi_ = ey + (w.x * oy + w.y * ox);
                    mg[j] = fmaxf(sqrtf(xr_ * xr_ + xi_ * xi_), 1e-8f);
                }
                if (t64 == 0) {
                    float2 Z0 = buf0[0];
                    mg[512] = fmaxf(fabsf(Z0.x - Z0.y), 1e-8f);
                }
            }
            __syncthreads();    // all three signals' magnitudes ready

            // ---- accumulate patch partial sums (all 192 threads) ----
            {
                const float* ms  = (const float*)SH[0][1];
                const float* mt  = (const float*)SH[1][1];
                const float* mgd = (const float*)SH[2][1];
                {
                    int f = tid;                       // 0..191
                    float s = ms[f], tt = mt[f], g = mgd[f];
                    aS0 += fabsf(s - g); aT0 += fabsf(tt - g);
                    float d = s - tt; aP0 += d * d;
                }
                {
                    int f = tid + 192;                 // 192..383
                    float s = ms[f], tt = mt[f], g = mgd[f];
                    aS1 += fabsf(s - g); aT1 += fabsf(tt - g);
                    float d = s - tt; aP1 += d * d;
                }
                if (tid + 384 < NF) {                  // 384..512
                    int f = tid + 384;
                    float s = ms[f], tt = mt[f], g = mgd[f];
                    aS2 += fabsf(s - g); aT2 += fabsf(tt - g);
                    float d = s - tt; aP2 += d * d;
                }
            }
            __syncthreads();   // protect bufs before next frame
        }

        // ---- fold per-thread accumulators into per-f-patch sums ----
        {
            int f0 = tid;
            atomicAdd(&pacc[f0 >> 4][0], aS0);
            atomicAdd(&pacc[f0 >> 4][1], aT0);
            atomicAdd(&pacc[f0 >> 4][2], aP0);
            int f1 = tid + 192;
            atomicAdd(&pacc[f1 >> 4][0], aS1);
            atomicAdd(&pacc[f1 >> 4][1], aT1);
            atomicAdd(&pacc[f1 >> 4][2], aP1);
            if (tid + 384 < NF) {
                int f2 = tid + 384;
                atomicAdd(&pacc[f2 >> 4][0], aS2);
                atomicAdd(&pacc[f2 >> 4][1], aT2);
                atomicAdd(&pacc[f2 >> 4][2], aP2);
            }
        }
        __syncthreads();

        if (tid < NFP) {
            // g_part layout: [pt][fp][3]
            size_t o = ((size_t)pt * NFP + tid) * 3;
            g_part[o + 0] = pacc[tid][0];
            g_part[o + 1] = pacc[tid][1];
            g_part[o + 2] = pacc[tid][2];
        }
        __syncthreads();   // pacc reusable next half
    }
}

// ---------------------------------------------------------------------------
// Kernel 3: per-batch top-k selection (exact, index-order tie-break) + stats
// ---------------------------------------------------------------------------
__device__ __forceinline__ int bredI(int v, int* scr) {
    const int tid = threadIdx.x;
#pragma unroll
    for (int o = 16; o; o >>= 1) v += __shfl_down_sync(0xffffffffu, v, o);
    __syncthreads();
    if ((tid & 31) == 0) scr[tid >> 5] = v;
    __syncthreads();
    int r = 0;
#pragma unroll
    for (int j = 0; j < 8; j++) r += scr[j];
    return r;
}
__device__ __forceinline__ float bredF(float v, float* scr) {
    const int tid = threadIdx.x;
#pragma unroll
    for (int o = 16; o; o >>= 1) v += __shfl_down_sync(0xffffffffu, v, o);
    __syncthreads();
    if ((tid & 31) == 0) scr[tid >> 5] = v;
    __syncthreads();
    float r = 0.f;
#pragma unroll
    for (int j = 0; j < 8; j++) r += scr[j];
    return r;
}

__global__ __launch_bounds__(256) void select_kernel() {
    const int b = blockIdx.x, tid = threadIdx.x;
    __shared__ unsigned su[NP];
    __shared__ float    spl[NP];
    __shared__ int      eqidx[NP];
    __shared__ int      iscr[8];
    __shared__ float    fscr[8];
    __shared__ int      eqc;

    float ksum = 0.f; int pcnt = 0;
    for (int i = tid; i < NP; i += 256) {
        int fp = i / NTP, tp = i - fp * NTP;       // patch order p = fp*NTP+tp
        const float* pp = g_part + ((size_t)(b * NTP + tp) * NFP + fp) * 3;
        float kv = (pp[0] - pp[1]) * (1.0f / 256.0f);
        spl[i] = pp[2] * (1.0f / 256.0f);
        unsigned bits = __float_as_uint(kv);
        su[i] = (bits & 0x80000000u) ? ~bits : (bits | 0x80000000u); // order-preserving
        ksum += kv;
        pcnt += (kv > 0.f) ? 1 : 0;
    }
    if (tid == 0) eqc = 0;
    __syncthreads();

    ksum = bredF(ksum, fscr);
    pcnt = bredI(pcnt, iscr);

    // binary search for k-th largest key: max v with count(u >= v) >= KSEL
    unsigned long long lo = 0ull, hi = 0xFFFFFFFFull;
    while (lo < hi) {
        unsigned long long mid = lo + ((hi - lo + 1ull) >> 1);
        int c = 0;
        for (int i = tid; i < NP; i += 256)
            c += ((unsigned long long)su[i] >= mid) ? 1 : 0;
        c = bredI(c, iscr);
        if (c >= KSEL) lo = mid; else hi = mid - 1ull;
    }
    const unsigned v = (unsigned)lo;

    int cgt = 0; float ssel = 0.f;
    for (int i = tid; i < NP; i += 256) {
        unsigned u = su[i];
        if (u > v) { cgt++; ssel += spl[i]; }
        else if (u == v) { int pos = atomicAdd(&eqc, 1); eqidx[pos] = i; }
    }
    cgt  = bredI(cgt, iscr);
    ssel = bredF(ssel, fscr);
    __syncthreads();

    if (tid == 0) {
        int need = KSEL - cgt;         // >= 1 by construction
        int ce   = eqc;
        float extra = 0.f;
        if (need >= ce) {
            for (int j = 0; j < ce; j++) extra += spl[eqidx[j]];
        } else {
            int last = -1;
            for (int t2 = 0; t2 < need; t2++) {
                int mn = 0x7fffffff;
                for (int j = 0; j < ce; j++) {
                    int ix = eqidx[j];
                    if (ix > last && ix < mn) mn = ix;
                }
                extra += spl[mn];
                last = mn;
            }
        }
        g_bsel[b] = (ssel + extra) * (1.0f / (float)KSEL);
        g_bkgs[b] = ksum;
        g_bpos[b] = pcnt;
    }
}

// ---------------------------------------------------------------------------
// Kernel 4: finalize the 4 scalars
// ---------------------------------------------------------------------------
__global__ void final_kernel(float* __restrict__ out) {
    const int t = threadIdx.x;
    float s  = (t < BATCH) ? g_bsel[t] : 0.f;
    float kg = (t < BATCH) ? g_bkgs[t] : 0.f;
    float pc = (t < BATCH) ? (float)g_bpos[t] : 0.f;
#pragma unroll
    for (int o = 16; o; o >>= 1) {
        s  += __shfl_down_sync(0xffffffffu, s,  o);
        kg += __shfl_down_sync(0xffffffffu, kg, o);
        pc += __shfl_down_sync(0xffffffffu, pc, o);
    }
    if (t == 0) {
        out[0] = s * (1.0f / (float)BATCH);                      // loss
        out[1] = (float)KSEL / (float)NP;                        // sel_ratio
        out[2] = kg / (float)(BATCH * NP);                       // kgs_mean
        out[3] = pc / (float)(BATCH * NP);                       // kgs_pos_ratio
    }
}

extern "C" void kernel_launch(void* const* d_in, const int* in_sizes, int n_in,
                              void* d_out, int out_size) {
    const float* xs = (const float*)d_in[0];
    const float* xt = (const float*)d_in[1];
    const float* xg = (const float*)d_in[2];
    float* out = (float*)d_out;

    init_tw<<<9, 128>>>();
    fused_kernel<<<520, 192>>>(xs, xt, xg);   // 520 blocks = ONE wave
    select_kernel<<<BATCH, 256>>>();
    final_kernel<<<1, 32>>>(out);
}